// round 3
// baseline (speedup 1.0000x reference)
#include <cuda_runtime.h>
#include <math.h>

#define BB 4
#define NSEQ 2048
#define DMODEL 1024
#define NHEADS 8
#define DH 128
#define NEG_INF_F (-1e9f)

// ---------------- scratch (device globals; no runtime allocation) ----------
__device__ float g_Q[BB*NHEADS*NSEQ*DH];                 // 33.5 MB
__device__ float g_K[BB*NHEADS*NSEQ*DH];
__device__ float g_V[BB*NHEADS*NSEQ*DH];
__device__ float g_E[134217728];                         // B*H*N*N = 512 MB
__device__ float g_AP[NSEQ*NSEQ];                        // 16.8 MB
__device__ float g_mx[BB*NHEADS*NSEQ];
__device__ float g_rinv[BB*NHEADS*NSEQ];
__device__ float g_Y[BB*NSEQ*DMODEL];                    // concat heads, 33.5 MB

// ---------------- K0: absolute position table ------------------------------
__global__ void __launch_bounds__(256) ap_kernel() {
    int idx = blockIdx.x * 256 + threadIdx.x;
    if (idx >= NSEQ * NSEQ) return;
    int p = idx / NSEQ, k = idx % NSEQ;
    float ex = (float)(k & ~1) / (float)DMODEL;     // 2i/d, i = k>>1
    float denom = powf(10000.0f, ex);
    float ang = (float)p / denom;
    g_AP[idx] = (k & 1) ? cosf(ang) : sinf(ang);
}

// ---------------- K1: QKV projection (C[2048,128] = X[2048,1024] * W[128,1024]^T)
__global__ void __launch_bounds__(256) proj_kernel(
    const float* __restrict__ x, const float* __restrict__ Wq,
    const float* __restrict__ Wk, const float* __restrict__ Wv) {
    int z = blockIdx.z;                      // b*(3H) + which*H + h
    int b = z / (3 * NHEADS);
    int r = z % (3 * NHEADS);
    int which = r / NHEADS;
    int h = r % NHEADS;
    const float* A = x + (size_t)b * NSEQ * DMODEL;
    const float* W = (which == 0 ? Wq : which == 1 ? Wk : Wv) + (size_t)h * DH * DMODEL;
    float* C = (which == 0 ? g_Q : which == 1 ? g_K : g_V) + (size_t)(b * NHEADS + h) * NSEQ * DH;

    int row0 = blockIdx.y * 64;
    int col0 = blockIdx.x * 64;              // within DH
    __shared__ float As[16][64];
    __shared__ float Bs[16][64];
    int tid = threadIdx.x;
    int tx = tid & 15, ty = tid >> 4;
    int ar = tid >> 2, ak4 = (tid & 3) * 4;
    float c[4][4] = {};

    for (int k0 = 0; k0 < DMODEL; k0 += 16) {
        float4 av = *(const float4*)&A[(size_t)(row0 + ar) * DMODEL + k0 + ak4];
        float4 bv = *(const float4*)&W[(size_t)(col0 + ar) * DMODEL + k0 + ak4];
        As[ak4+0][ar]=av.x; As[ak4+1][ar]=av.y; As[ak4+2][ar]=av.z; As[ak4+3][ar]=av.w;
        Bs[ak4+0][ar]=bv.x; Bs[ak4+1][ar]=bv.y; Bs[ak4+2][ar]=bv.z; Bs[ak4+3][ar]=bv.w;
        __syncthreads();
        #pragma unroll
        for (int kk = 0; kk < 16; kk++) {
            float a_[4], b_[4];
            *(float4*)a_ = *(const float4*)&As[kk][ty * 4];
            *(float4*)b_ = *(const float4*)&Bs[kk][tx * 4];
            #pragma unroll
            for (int ii = 0; ii < 4; ii++)
                #pragma unroll
                for (int jj = 0; jj < 4; jj++)
                    c[ii][jj] = fmaf(a_[ii], b_[jj], c[ii][jj]);
        }
        __syncthreads();
    }
    #pragma unroll
    for (int ii = 0; ii < 4; ii++)
        #pragma unroll
        for (int jj = 0; jj < 4; jj++)
            C[(size_t)(row0 + ty * 4 + ii) * DH + col0 + tx * 4 + jj] = c[ii][jj];
}

// ---------------- K2: E = Q K^T + AP, masked -------------------------------
__global__ void __launch_bounds__(256) qk_kernel(const int* __restrict__ mask) {
    int bh = blockIdx.z;
    int b = bh / NHEADS;
    const float* Qp = g_Q + (size_t)bh * NSEQ * DH;
    const float* Kp = g_K + (size_t)bh * NSEQ * DH;
    int row0 = blockIdx.y * 64;   // query j
    int col0 = blockIdx.x * 64;   // key i
    __shared__ float As[16][64];
    __shared__ float Bs[16][64];
    int tid = threadIdx.x;
    int tx = tid & 15, ty = tid >> 4;
    int ar = tid >> 2, ak4 = (tid & 3) * 4;
    float c[4][4] = {};

    for (int k0 = 0; k0 < DH; k0 += 16) {
        float4 av = *(const float4*)&Qp[(size_t)(row0 + ar) * DH + k0 + ak4];
        float4 bv = *(const float4*)&Kp[(size_t)(col0 + ar) * DH + k0 + ak4];
        As[ak4+0][ar]=av.x; As[ak4+1][ar]=av.y; As[ak4+2][ar]=av.z; As[ak4+3][ar]=av.w;
        Bs[ak4+0][ar]=bv.x; Bs[ak4+1][ar]=bv.y; Bs[ak4+2][ar]=bv.z; Bs[ak4+3][ar]=bv.w;
        __syncthreads();
        #pragma unroll
        for (int kk = 0; kk < 16; kk++) {
            float a_[4], b_[4];
            *(float4*)a_ = *(const float4*)&As[kk][ty * 4];
            *(float4*)b_ = *(const float4*)&Bs[kk][tx * 4];
            #pragma unroll
            for (int ii = 0; ii < 4; ii++)
                #pragma unroll
                for (int jj = 0; jj < 4; jj++)
                    c[ii][jj] = fmaf(a_[ii], b_[jj], c[ii][jj]);
        }
        __syncthreads();
    }
    const int* mrow = mask + b * NSEQ;
    #pragma unroll
    for (int ii = 0; ii < 4; ii++) {
        int j = row0 + ty * 4 + ii;
        int mj = __ldg(&mrow[j]);
        float* erow = g_E + ((size_t)bh * NSEQ + j) * NSEQ;
        const float* aprow = g_AP + (size_t)j * NSEQ;
        #pragma unroll
        for (int jj = 0; jj < 4; jj++) {
            int i = col0 + tx * 4 + jj;
            int mi = __ldg(&mrow[i]);
            erow[i] = (mj && mi) ? c[ii][jj] + aprow[i] : NEG_INF_F;
        }
    }
}

// ---------------- K3: per-row max + 1/sum(exp) -----------------------------
__global__ void __launch_bounds__(256) stats_kernel() {
    size_t row = blockIdx.x;
    const float* e = g_E + row * NSEQ;
    int t = threadIdx.x;
    float v[8];
    float mx = -INFINITY;
    #pragma unroll
    for (int i = 0; i < 8; i++) { v[i] = e[t + (i << 8)]; mx = fmaxf(mx, v[i]); }
    __shared__ float sred[8];
    #pragma unroll
    for (int o = 16; o; o >>= 1) mx = fmaxf(mx, __shfl_xor_sync(0xffffffffu, mx, o));
    if ((t & 31) == 0) sred[t >> 5] = mx;
    __syncthreads();
    if (t == 0) {
        float m = sred[0];
        #pragma unroll
        for (int i = 1; i < 8; i++) m = fmaxf(m, sred[i]);
        sred[0] = m;
    }
    __syncthreads();
    mx = sred[0];
    __syncthreads();
    float s = 0.f;
    #pragma unroll
    for (int i = 0; i < 8; i++) s += __expf(v[i] - mx);
    #pragma unroll
    for (int o = 16; o; o >>= 1) s += __shfl_xor_sync(0xffffffffu, s, o);
    if ((t & 31) == 0) sred[t >> 5] = s;
    __syncthreads();
    if (t == 0) {
        float tot = 0.f;
        #pragma unroll
        for (int i = 0; i < 8; i++) tot += sred[i];
        g_mx[row] = mx;
        g_rinv[row] = 1.0f / tot;
    }
}

// ---------------- K4: Y[i,e] = sum_j A[j,i] V[j,e]; A written out for h=7 ---
__global__ void __launch_bounds__(256) av_kernel(float* __restrict__ outA) {
    int bh = blockIdx.z;
    int b = bh / NHEADS, h = bh % NHEADS;
    const float* E = g_E + (size_t)bh * NSEQ * NSEQ;
    const float* V = g_V + (size_t)bh * NSEQ * DH;
    const float* mxp = g_mx + bh * NSEQ;
    const float* rip = g_rinv + bh * NSEQ;
    int i0b = blockIdx.y * 64;            // output row (key index) tile
    __shared__ float As[16][64];          // a[j][i]
    __shared__ float Bs[16][128];         // V[j][e]
    int tid = threadIdx.x;
    int tx = tid & 15, ty = tid >> 4;
    int ajj = tid >> 4, ai4 = (tid & 15) * 4;
    bool wA = (h == NHEADS - 1) && (outA != nullptr);
    float c[4][8] = {};

    for (int j0 = 0; j0 < NSEQ; j0 += 16) {
        int j = j0 + ajj;
        float mxj = mxp[j], rj = rip[j];
        float4 ev = *(const float4*)&E[(size_t)j * NSEQ + i0b + ai4];
        float4 a4;
        a4.x = __expf(ev.x - mxj) * rj;
        a4.y = __expf(ev.y - mxj) * rj;
        a4.z = __expf(ev.z - mxj) * rj;
        a4.w = __expf(ev.w - mxj) * rj;
        if (wA) *(float4*)&outA[((size_t)b * NSEQ + j) * NSEQ + i0b + ai4] = a4;
        *(float4*)&As[ajj][ai4] = a4;
        #pragma unroll
        for (int p = 0; p < 2; p++) {
            int idx = tid + p * 256;
            int vj = idx >> 5;
            int e4 = (idx & 31) * 4;
            *(float4*)&Bs[vj][e4] = *(const float4*)&V[(size_t)(j0 + vj) * DH + e4];
        }
        __syncthreads();
        #pragma unroll
        for (int kk = 0; kk < 16; kk++) {
            float a_[4], b_[8];
            *(float4*)a_ = *(const float4*)&As[kk][ty * 4];
            *(float4*)&b_[0] = *(const float4*)&Bs[kk][tx * 8];
            *(float4*)&b_[4] = *(const float4*)&Bs[kk][tx * 8 + 4];
            #pragma unroll
            for (int ii = 0; ii < 4; ii++)
                #pragma unroll
                for (int jj = 0; jj < 8; jj++)
                    c[ii][jj] = fmaf(a_[ii], b_[jj], c[ii][jj]);
        }
        __syncthreads();
    }
    #pragma unroll
    for (int ii = 0; ii < 4; ii++) {
        int ig = i0b + ty * 4 + ii;
        float* yrow = g_Y + ((size_t)b * NSEQ + ig) * DMODEL + h * DH + tx * 8;
        #pragma unroll
        for (int jj = 0; jj < 8; jj++) yrow[jj] = c[ii][jj];
    }
}

// ---------------- K5: out = Y @ Wout^T -------------------------------------
__global__ void __launch_bounds__(256) out_kernel(const float* __restrict__ W,
                                                  float* __restrict__ C) {
    int row0 = blockIdx.y * 64;    // over B*N = 8192 rows
    int col0 = blockIdx.x * 64;    // over 1024 out features
    __shared__ float As[16][64];
    __shared__ float Bs[16][64];
    int tid = threadIdx.x;
    int tx = tid & 15, ty = tid >> 4;
    int ar = tid >> 2, ak4 = (tid & 3) * 4;
    float c[4][4] = {};

    for (int k0 = 0; k0 < DMODEL; k0 += 16) {
        float4 av = *(const float4*)&g_Y[(size_t)(row0 + ar) * DMODEL + k0 + ak4];
        float4 bv = *(const float4*)&W[(size_t)(col0 + ar) * DMODEL + k0 + ak4];
        As[ak4+0][ar]=av.x; As[ak4+1][ar]=av.y; As[ak4+2][ar]=av.z; As[ak4+3][ar]=av.w;
        Bs[ak4+0][ar]=bv.x; Bs[ak4+1][ar]=bv.y; Bs[ak4+2][ar]=bv.z; Bs[ak4+3][ar]=bv.w;
        __syncthreads();
        #pragma unroll
        for (int kk = 0; kk < 16; kk++) {
            float a_[4], b_[4];
            *(float4*)a_ = *(const float4*)&As[kk][ty * 4];
            *(float4*)b_ = *(const float4*)&Bs[kk][tx * 4];
            #pragma unroll
            for (int ii = 0; ii < 4; ii++)
                #pragma unroll
                for (int jj = 0; jj < 4; jj++)
                    c[ii][jj] = fmaf(a_[ii], b_[jj], c[ii][jj]);
        }
        __syncthreads();
    }
    #pragma unroll
    for (int ii = 0; ii < 4; ii++)
        #pragma unroll
        for (int jj = 0; jj < 4; jj++)
            C[(size_t)(row0 + ty * 4 + ii) * DMODEL + col0 + tx * 4 + jj] = c[ii][jj];
}

// ---------------- launch ----------------------------------------------------
extern "C" void kernel_launch(void* const* d_in, const int* in_sizes, int n_in,
                              void* d_out, int out_size) {
    const float* x    = (const float*)d_in[0];
    const int*   mask = (const int*)d_in[1];
    const float* Wq   = (const float*)d_in[2];
    const float* Wk   = (const float*)d_in[3];
    const float* Wv   = (const float*)d_in[4];
    const float* Wout = (const float*)d_in[5];
    float* out = (float*)d_out;

    const long long out_elems = (long long)BB * NSEQ * DMODEL;                 // 8388608
    const long long att_elems = (long long)BB * NSEQ * NSEQ;                   // 16777216
    float* outA = ((long long)out_size >= out_elems + att_elems)
                      ? out + out_elems : nullptr;

    ap_kernel<<<(NSEQ * NSEQ) / 256, 256>>>();
    proj_kernel<<<dim3(DH / 64, NSEQ / 64, BB * 3 * NHEADS), 256>>>(x, Wq, Wk, Wv);
    qk_kernel<<<dim3(NSEQ / 64, NSEQ / 64, BB * NHEADS), 256>>>(mask);
    stats_kernel<<<BB * NHEADS * NSEQ, 256>>>();
    av_kernel<<<dim3(1, NSEQ / 64, BB * NHEADS), 256>>>(outA);
    out_kernel<<<dim3(DMODEL / 64, (BB * NSEQ) / 64, 1), 256>>>(Wout, out);
}

// round 8
// speedup vs baseline: 2.5773x; 2.5773x over previous
#include <cuda_runtime.h>
#include <cuda_bf16.h>
#include <math.h>
#include <stdint.h>

#define BB 4
#define NSEQ 2048
#define DMODEL 1024
#define NHEADS 8
#define DH 128

// ----------------------------- scratch (device globals) --------------------
__device__ float g_E[134217728];                                  // B*H*N*N fp32
__device__ float g_P[BB * NSEQ * 3072];                           // proj out [8192][3072]
__device__ float g_Y[BB * NSEQ * DMODEL];
__device__ float g_AP[NSEQ * NSEQ];
__device__ float g_mx[BB * NHEADS * NSEQ];
__device__ float g_rinv[BB * NHEADS * NSEQ];
__device__ __align__(128) __nv_bfloat16 g_xaug[8192 * 3072];      // A-side
__device__ __align__(128) __nv_bfloat16 g_Waug[3072 * 3072];      // B-side (Wq|Wk|Wv rows)
__device__ __align__(128) __nv_bfloat16 g_Woutaug[1024 * 3072];   // B-side
__device__ __align__(128) __nv_bfloat16 g_Qaug[32 * 2048 * 384];  // A-side
__device__ __align__(128) __nv_bfloat16 g_Kaug[32 * 2048 * 384];  // B-side
__device__ __align__(128) __nv_bfloat16 g_Vaug[32 * 128 * 6144];  // B-side (V^T)
__device__ __align__(128) __nv_bfloat16 g_At[402653184];          // 32*2048*6144, A-side (A^T)
__device__ __align__(128) __nv_bfloat16 g_Yaug[8192 * 3072];      // A-side

// ----------------------------- PTX helpers (baseline features only) --------
__device__ __forceinline__ uint32_t smem_u32(const void* p) {
    uint32_t a;
    asm("{ .reg .u64 t; cvta.to.shared.u64 t, %1; cvt.u32.u64 %0, t; }" : "=r"(a) : "l"(p));
    return a;
}
__device__ __forceinline__ void cp16(uint32_t s, const void* g) {
    asm volatile("cp.async.cg.shared.global [%0], [%1], 16;" :: "r"(s), "l"(g));
}
__device__ __forceinline__ void cp_commit() {
    asm volatile("cp.async.commit_group;" ::: "memory");
}
__device__ __forceinline__ void cp_wait1() {
    asm volatile("cp.async.wait_group 1;" ::: "memory");
}
__device__ __forceinline__ void cp_wait0() {
    asm volatile("cp.async.wait_group 0;" ::: "memory");
}
__device__ __forceinline__ void ldsm4(uint32_t* r, uint32_t addr) {
    asm volatile("ldmatrix.sync.aligned.m8n8.x4.shared.b16 {%0,%1,%2,%3}, [%4];"
        : "=r"(r[0]), "=r"(r[1]), "=r"(r[2]), "=r"(r[3]) : "r"(addr));
}
__device__ __forceinline__ void mma16816(float* d, const uint32_t* a, const uint32_t* b) {
    asm volatile(
        "mma.sync.aligned.m16n8k16.row.col.f32.bf16.bf16.f32 "
        "{%0,%1,%2,%3}, {%4,%5,%6,%7}, {%8,%9}, {%0,%1,%2,%3};"
        : "+f"(d[0]), "+f"(d[1]), "+f"(d[2]), "+f"(d[3])
        : "r"(a[0]), "r"(a[1]), "r"(a[2]), "r"(a[3]), "r"(b[0]), "r"(b[1]));
}

// ----------------------------- K0: AP table --------------------------------
__global__ void __launch_bounds__(256) ap_kernel() {
    int idx = blockIdx.x * 256 + threadIdx.x;
    if (idx >= NSEQ * NSEQ) return;
    int p = idx / NSEQ, k = idx % NSEQ;
    float ex = (float)(k & ~1) / (float)DMODEL;
    float denom = powf(10000.0f, ex);
    float ang = (float)p / denom;
    g_AP[idx] = (k & 1) ? cosf(ang) : sinf(ang);
}

// ----------------------------- split (fp32 -> augmented bf16) ---------------
// modeA=1: (hi, lo, hi)   modeA=0: (hi, hi, lo)
__global__ void __launch_bounds__(256) split_kernel(const float* __restrict__ S,
                                                    __nv_bfloat16* __restrict__ D,
                                                    int K, int modeA, int total) {
    int idx = blockIdx.x * 256 + threadIdx.x;
    if (idx >= total) return;
    int r = idx / K, k = idx - r * K;
    float v = S[idx];
    __nv_bfloat16 hi = __float2bfloat16(v);
    __nv_bfloat16 lo = __float2bfloat16(v - __bfloat162float(hi));
    long base = (long)r * 3 * K;
    if (modeA) {
        D[base + k] = hi; D[base + K + k] = lo; D[base + 2 * K + k] = hi;
    } else {
        D[base + k] = hi; D[base + K + k] = hi; D[base + 2 * K + k] = lo;
    }
}

// ----------------------------- Q/K aug from g_P -----------------------------
__global__ void __launch_bounds__(256) qksplit_kernel() {
    int idx = blockIdx.x * 256 + threadIdx.x;   // 2^23 total
    int e = idx & 127;
    int n = (idx >> 7) & 2047;
    int h = (idx >> 18) & 7;
    int b = idx >> 21;
    const float* P = g_P + ((long)(b * NSEQ + n)) * 3072 + h * DH + e;
    float q = P[0], k = P[1024];
    long base = ((long)(b * NHEADS + h) * NSEQ + n) * 384 + e;
    __nv_bfloat16 qh = __float2bfloat16(q);
    __nv_bfloat16 ql = __float2bfloat16(q - __bfloat162float(qh));
    g_Qaug[base] = qh; g_Qaug[base + 128] = ql; g_Qaug[base + 256] = qh;   // A-side
    __nv_bfloat16 kh = __float2bfloat16(k);
    __nv_bfloat16 kl = __float2bfloat16(k - __bfloat162float(kh));
    g_Kaug[base] = kh; g_Kaug[base + 128] = kh; g_Kaug[base + 256] = kl;   // B-side
}

// ----------------------------- V^T aug (tiled transpose) --------------------
__global__ void __launch_bounds__(256) vtrans_kernel() {
    int bh = blockIdx.z;
    int b = bh >> 3, h = bh & 7;
    int j0 = blockIdx.x * 32, e0 = blockIdx.y * 32;
    __shared__ float tile[32][33];
    int tx = threadIdx.x & 31, ty = threadIdx.x >> 5;
    #pragma unroll
    for (int p = 0; p < 4; p++) {
        int j = j0 + ty + p * 8;
        tile[ty + p * 8][tx] = g_P[((long)(b * NSEQ + j)) * 3072 + 2048 + h * DH + e0 + tx];
    }
    __syncthreads();
    __nv_bfloat16* V = g_Vaug + (long)bh * 128 * 6144;
    #pragma unroll
    for (int p = 0; p < 4; p++) {
        int e = e0 + ty + p * 8;
        float v = tile[tx][ty + p * 8];
        __nv_bfloat16 hi = __float2bfloat16(v);
        __nv_bfloat16 lo = __float2bfloat16(v - __bfloat162float(hi));
        long base = (long)e * 6144 + j0 + tx;
        V[base] = hi; V[base + 2048] = hi; V[base + 4096] = lo;            // B-side
    }
}

// ----------------------------- stats (row max + 1/sum exp) ------------------
__global__ void __launch_bounds__(256) stats_kernel() {
    size_t row = blockIdx.x;
    const float* e = g_E + row * NSEQ;
    int t = threadIdx.x;
    float v[8];
    float mx = -INFINITY;
    #pragma unroll
    for (int i = 0; i < 8; i++) { v[i] = e[t + (i << 8)]; mx = fmaxf(mx, v[i]); }
    __shared__ float sred[8];
    #pragma unroll
    for (int o = 16; o; o >>= 1) mx = fmaxf(mx, __shfl_xor_sync(0xffffffffu, mx, o));
    if ((t & 31) == 0) sred[t >> 5] = mx;
    __syncthreads();
    if (t == 0) {
        float m = sred[0];
        #pragma unroll
        for (int i = 1; i < 8; i++) m = fmaxf(m, sred[i]);
        sred[0] = m;
    }
    __syncthreads();
    mx = sred[0];
    __syncthreads();
    float s = 0.f;
    #pragma unroll
    for (int i = 0; i < 8; i++) s += __expf(v[i] - mx);
    #pragma unroll
    for (int o = 16; o; o >>= 1) s += __shfl_xor_sync(0xffffffffu, s, o);
    if ((t & 31) == 0) sred[t >> 5] = s;
    __syncthreads();
    if (t == 0) {
        float tot = 0.f;
        #pragma unroll
        for (int i = 0; i < 8; i++) tot += sred[i];
        g_mx[row] = mx;
        g_rinv[row] = 1.0f / tot;
    }
}

// ---------------- A^T aug from E (+ fp32 attention output for h=7) ----------
__global__ void __launch_bounds__(256) at_kernel(float* __restrict__ outA) {
    int bh = blockIdx.z;
    int b = bh >> 3, h = bh & 7;
    int j0 = blockIdx.y * 32, i0 = blockIdx.x * 32;
    __shared__ float tile[32][33];
    const float* E = g_E + (long)bh * NSEQ * NSEQ;
    const float* mxp = g_mx + bh * NSEQ;
    const float* rp = g_rinv + bh * NSEQ;
    int tx = threadIdx.x & 31, ty = threadIdx.x >> 5;
    bool wA = (h == NHEADS - 1) && (outA != nullptr);
    #pragma unroll
    for (int p = 0; p < 4; p++) {
        int j = j0 + ty + p * 8;
        float a = __expf(E[(long)j * NSEQ + i0 + tx] - mxp[j]) * rp[j];
        tile[ty + p * 8][tx] = a;
        if (wA) outA[((long)b * NSEQ + j) * NSEQ + i0 + tx] = a;
    }
    __syncthreads();
    __nv_bfloat16* At = g_At + (long)bh * NSEQ * 6144;
    #pragma unroll
    for (int p = 0; p < 4; p++) {
        int i = i0 + ty + p * 8;
        float v = tile[tx][ty + p * 8];
        __nv_bfloat16 hi = __float2bfloat16(v);
        __nv_bfloat16 lo = __float2bfloat16(v - __bfloat162float(hi));
        long base = (long)i * 6144 + j0 + tx;
        At[base] = hi; At[base + 2048] = lo; At[base + 4096] = hi;         // A-side
    }
}

// ----------------------------- HMMA GEMM (baseline mma.sync) -----------------
// C[m0+128][n0+128] (per z) = sum_k A[m][k] * B[n][k], bf16 in / fp32 out.
// mode 0: plain store. mode 1: E epilogue (+AP, mask). mode 2: Y scatter.
// Tile: 128x128, BK=64 bf16 (128B rows), double-buffered cp.async, SW128 swizzle.
#define GSMEM 65536

__global__ void __launch_bounds__(256) gemm_kernel(
    const __nv_bfloat16* __restrict__ A, long sAz, int lda,
    const __nv_bfloat16* __restrict__ B, long sBz, int ldb,
    int Ktot, int mode, float* __restrict__ C, long sCz, int ldc,
    const int* __restrict__ mask) {
    extern __shared__ char smem[];
    uint32_t sbase = smem_u32(smem);
    int tid = threadIdx.x, wid = tid >> 5, lane = tid & 31;
    int n0 = blockIdx.x * 128, m0 = blockIdx.y * 128, z = blockIdx.z;

    const __nv_bfloat16* Az = A + (long)z * sAz + (long)m0 * lda;
    const __nv_bfloat16* Bz = B + (long)z * sBz + (long)n0 * ldb;

    int warp_m = (wid & 3) * 32;
    int warp_n = (wid >> 2) * 64;

    float acc[2][8][4];
    #pragma unroll
    for (int i = 0; i < 2; i++)
        #pragma unroll
        for (int j = 0; j < 8; j++)
            #pragma unroll
            for (int k = 0; k < 4; k++) acc[i][j][k] = 0.f;

    // per-thread ldmatrix address components
    uint32_t aoff[2], boff[4];
    #pragma unroll
    for (int mi = 0; mi < 2; mi++)
        aoff[mi] = (uint32_t)(warp_m + mi * 16 + (lane & 15)) * 128;
    uint32_t ake = ((lane >> 4) & 1) * 16;          // bytes (k half)
    #pragma unroll
    for (int bi = 0; bi < 4; bi++)
        boff[bi] = (uint32_t)(warp_n + bi * 16 + (lane & 7) + ((lane >> 4) & 1) * 8) * 128;
    uint32_t bke = ((lane >> 3) & 1) * 16;

    int nchunk = Ktot >> 6;

    // ---- load chunk ic into buffer buf
    int ld_rr = tid >> 3;          // 0..31 rows per pass (x4 passes -> 128)
    int ld_cc = tid & 7;           // 16B chunk within 128B row
    #define LOAD_CHUNK(ic, buf) do {                                          \
        const __nv_bfloat16* As_ = Az + (long)(ic) * 64;                      \
        const __nv_bfloat16* Bs_ = Bz + (long)(ic) * 64;                      \
        uint32_t base_ = sbase + (buf) * 32768;                               \
        _Pragma("unroll")                                                     \
        for (int t_ = 0; t_ < 4; t_++) {                                      \
            int rr_ = ld_rr + t_ * 32;                                        \
            uint32_t off_ = (uint32_t)rr_ * 128 + ld_cc * 16;                 \
            uint32_t sw_ = off_ ^ ((off_ >> 3) & 0x70);                       \
            cp16(base_ + sw_, As_ + (long)rr_ * lda + ld_cc * 8);             \
            cp16(base_ + 16384 + sw_, Bs_ + (long)rr_ * ldb + ld_cc * 8);     \
        }                                                                     \
        cp_commit();                                                          \
    } while (0)

    LOAD_CHUNK(0, 0);
    for (int ic = 0; ic < nchunk; ic++) {
        int buf = ic & 1;
        if (ic + 1 < nchunk) { LOAD_CHUNK(ic + 1, buf ^ 1); cp_wait1(); }
        else cp_wait0();
        __syncthreads();

        uint32_t aB = sbase + buf * 32768;
        uint32_t bB = aB + 16384;
        #pragma unroll
        for (int ks = 0; ks < 4; ks++) {
            uint32_t kcol = (uint32_t)ks * 32;
            uint32_t afr[2][4], bfr[4][4];
            #pragma unroll
            for (int mi = 0; mi < 2; mi++) {
                uint32_t off = aoff[mi] + kcol + ake;
                ldsm4(afr[mi], aB + (off ^ ((off >> 3) & 0x70)));
            }
            #pragma unroll
            for (int bi = 0; bi < 4; bi++) {
                uint32_t off = boff[bi] + kcol + bke;
                ldsm4(bfr[bi], bB + (off ^ ((off >> 3) & 0x70)));
            }
            #pragma unroll
            for (int mi = 0; mi < 2; mi++)
                #pragma unroll
                for (int ni = 0; ni < 8; ni++)
                    mma16816(acc[mi][ni], afr[mi], &bfr[ni >> 1][(ni & 1) * 2]);
        }
        __syncthreads();
    }

    // ---- epilogue
    float* Cz;
    if (mode == 2) Cz = C + (long)(z >> 3) * NSEQ * DMODEL + (z & 7) * DH;
    else           Cz = C + (long)z * sCz;

    if (mode == 1) {
        int b = z >> 3;
        #pragma unroll
        for (int mi = 0; mi < 2; mi++) {
            int r0 = m0 + warp_m + mi * 16 + (lane >> 2);
            int r1 = r0 + 8;
            int mj0 = __ldg(&mask[b * NSEQ + r0]);
            int mj1 = __ldg(&mask[b * NSEQ + r1]);
            #pragma unroll
            for (int ni = 0; ni < 8; ni++) {
                int col = n0 + warp_n + ni * 8 + (lane & 3) * 2;
                int2 mi2 = *(const int2*)&mask[b * NSEQ + col];
                float2 ap0 = *(const float2*)&g_AP[(long)r0 * NSEQ + col];
                float2 ap1 = *(const float2*)&g_AP[(long)r1 * NSEQ + col];
                float2 o0, o1;
                o0.x = (mj0 && mi2.x) ? acc[mi][ni][0] + ap0.x : -1e9f;
                o0.y = (mj0 && mi2.y) ? acc[mi][ni][1] + ap0.y : -1e9f;
                o1.x = (mj1 && mi2.x) ? acc[mi][ni][2] + ap1.x : -1e9f;
                o1.y = (mj1 && mi2.y) ? acc[mi][ni][3] + ap1.y : -1e9f;
                *(float2*)&Cz[(long)r0 * ldc + col] = o0;
                *(float2*)&Cz[(long)r1 * ldc + col] = o1;
            }
        }
    } else {
        #pragma unroll
        for (int mi = 0; mi < 2; mi++) {
            int r0 = m0 + warp_m + mi * 16 + (lane >> 2);
            int r1 = r0 + 8;
            #pragma unroll
            for (int ni = 0; ni < 8; ni++) {
                int col = n0 + warp_n + ni * 8 + (lane & 3) * 2;
                *(float2*)&Cz[(long)r0 * ldc + col] = make_float2(acc[mi][ni][0], acc[mi][ni][1]);
                *(float2*)&Cz[(long)r1 * ldc + col] = make_float2(acc[mi][ni][2], acc[mi][ni][3]);
            }
        }
    }
}

// ----------------------------- launch ---------------------------------------
extern "C" void kernel_launch(void* const* d_in, const int* in_sizes, int n_in,
                              void* d_out, int out_size) {
    const float* x    = (const float*)d_in[0];
    const int*   mask = (const int*)d_in[1];
    const float* Wq   = (const float*)d_in[2];
    const float* Wk   = (const float*)d_in[3];
    const float* Wv   = (const float*)d_in[4];
    const float* Wout = (const float*)d_in[5];
    float* out = (float*)d_out;

    const long long out_elems = (long long)BB * NSEQ * DMODEL;
    const long long att_elems = (long long)BB * NSEQ * NSEQ;
    float* outA = ((long long)out_size >= out_elems + att_elems) ? out + out_elems : nullptr;

    cudaFuncSetAttribute(gemm_kernel, cudaFuncAttributeMaxDynamicSharedMemorySize, GSMEM);

    __nv_bfloat16 *p_xaug, *p_Waug, *p_Woutaug, *p_Qaug, *p_Kaug, *p_Vaug, *p_At, *p_Yaug;
    float *p_P, *p_E, *p_Y;
    cudaGetSymbolAddress((void**)&p_xaug, g_xaug);
    cudaGetSymbolAddress((void**)&p_Waug, g_Waug);
    cudaGetSymbolAddress((void**)&p_Woutaug, g_Woutaug);
    cudaGetSymbolAddress((void**)&p_Qaug, g_Qaug);
    cudaGetSymbolAddress((void**)&p_Kaug, g_Kaug);
    cudaGetSymbolAddress((void**)&p_Vaug, g_Vaug);
    cudaGetSymbolAddress((void**)&p_At, g_At);
    cudaGetSymbolAddress((void**)&p_Yaug, g_Yaug);
    cudaGetSymbolAddress((void**)&p_P, g_P);
    cudaGetSymbolAddress((void**)&p_E, g_E);
    cudaGetSymbolAddress((void**)&p_Y, g_Y);

    ap_kernel<<<(NSEQ * NSEQ) / 256, 256>>>();

    // splits of inputs
    split_kernel<<<(8192 * 1024) / 256, 256>>>(x, p_xaug, 1024, 1, 8192 * 1024);
    split_kernel<<<(1024 * 1024) / 256, 256>>>(Wq,   p_Waug,                  1024, 0, 1024 * 1024);
    split_kernel<<<(1024 * 1024) / 256, 256>>>(Wk,   p_Waug + 1024 * 3072,    1024, 0, 1024 * 1024);
    split_kernel<<<(1024 * 1024) / 256, 256>>>(Wv,   p_Waug + 2048 * 3072,    1024, 0, 1024 * 1024);
    split_kernel<<<(1024 * 1024) / 256, 256>>>(Wout, p_Woutaug,               1024, 0, 1024 * 1024);

    // QKV projection: [8192,3072-aug] x [3072,3072-aug]^T
    gemm_kernel<<<dim3(3072 / 128, 8192 / 128, 1), 256, GSMEM>>>(
        p_xaug, 0, 3072, p_Waug, 0, 3072, 3072, 0, p_P, 0, 3072, mask);

    qksplit_kernel<<<(1 << 23) / 256, 256>>>();
    vtrans_kernel<<<dim3(NSEQ / 32, DH / 32, 32), 256>>>();

    // E = Q K^T + AP, masked
    gemm_kernel<<<dim3(NSEQ / 128, NSEQ / 128, 32), 256, GSMEM>>>(
        p_Qaug, (long)NSEQ * 384, 384, p_Kaug, (long)NSEQ * 384, 384,
        384, 1, p_E, (long)NSEQ * NSEQ, NSEQ, mask);

    stats_kernel<<<BB * NHEADS * NSEQ, 256>>>();
    at_kernel<<<dim3(NSEQ / 32, NSEQ / 32, 32), 256>>>(outA);

    // Y = A^T V
    gemm_kernel<<<dim3(1, NSEQ / 128, 32), 256, GSMEM>>>(
        p_At, (long)NSEQ * 6144, 6144, p_Vaug, (long)DH * 6144, 6144,
        6144, 2, p_Y, 0, DMODEL, mask);

    split_kernel<<<(8192 * 1024) / 256, 256>>>(p_Y, p_Yaug, 1024, 1, 8192 * 1024);

    // out = Y Wout^T
    gemm_kernel<<<dim3(1024 / 128, 8192 / 128, 1), 256, GSMEM>>>(
        p_Yaug, 0, 3072, p_Woutaug, 0, 3072, 3072, 0, out, 0, 1024, mask);
}